// round 7
// baseline (speedup 1.0000x reference)
#include <cuda_runtime.h>
#include <cuda_bf16.h>

// TenHotEncodeLayer: out[n, t, x[n,t,f]] = 1.0 for f in [0,10); all else 0.
// x: [32, 512, 10] int32, out: [32, 512, 5000] float32 (flat 81,920,000).
//
// Strategy v7: PERSISTENT single-wave grid over aligned flat ranges.
//   - 1184 CTAs (148 SMs x 8 resident CTAs) — exactly one wave, zero
//     wave-transition overhead. Each CTA grid-strides over aligned
//     2560-float4 (10240 B = 80 L2-line) ranges: 8000 ranges total.
//   - Per range: prefetch the <=30 candidate indices of the <=3 rows the
//     range intersects, stream 10 x STG.128 (evict-first) per thread,
//     block barrier, patch in-range positions with 1.0f (L2-hot).

#define NUM_TOKENS 5000
#define NUM_F 10
#define TPB 256
#define CTA_F4 2560                    // 10240 B, 128B-aligned
#define CTA_ELEMS (CTA_F4 * 4)
#define ITERS (CTA_F4 / TPB)           // 10, exact
#define NRANGES 8000                   // 20,480,000 f4 / 2560
#define GRID 1184                      // 148 * 8 — one wave

__global__ __launch_bounds__(TPB) void tenhot_kernel(
    const int* __restrict__ x, float4* __restrict__ out)
{
    const int tid = threadIdx.x;
    const float4 z = make_float4(0.f, 0.f, 0.f, 0.f);

    for (int blk = blockIdx.x; blk < NRANGES; blk += GRID) {
        // Flat element range owned this iteration: [s, s + CTA_ELEMS)
        const long long s = (long long)blk * CTA_ELEMS;
        const int row_lo = (int)(s / NUM_TOKENS);
        const int row_hi = (int)((s + CTA_ELEMS - 1) / NUM_TOKENS);
        const int npatch = (row_hi - row_lo + 1) * NUM_F;   // <= 30

        // Prefetch scatter candidates before the fill (latency hidden).
        long long flat = -1;
        if (tid < npatch) {
            int r = row_lo + tid / NUM_F;
            int f = tid - (tid / NUM_F) * NUM_F;
            int c = __ldg(&x[r * NUM_F + f]);
            long long p = (long long)r * NUM_TOKENS + c;
            if (p >= s && p < s + CTA_ELEMS) flat = p;
        }

        // Aligned streaming fill: 10 x STG.128, each warp op = 4 full lines.
        float4* o = out + (size_t)blk * CTA_F4;
#pragma unroll
        for (int k = 0; k < ITERS; k++)
            __stcs(&o[tid + TPB * k], z);

        __syncthreads();

        if (flat >= 0)
            reinterpret_cast<float*>(out)[flat] = 1.0f;

        // No second barrier needed: next iteration's writes target a
        // disjoint range; the patch store needs no ordering vs them.
    }
}

extern "C" void kernel_launch(void* const* d_in, const int* in_sizes, int n_in,
                              void* d_out, int out_size)
{
    const int* x = (const int*)d_in[0];
    float4* out = (float4*)d_out;
    tenhot_kernel<<<GRID, TPB>>>(x, out);
}

// round 8
// speedup vs baseline: 1.1193x; 1.1193x over previous
#include <cuda_runtime.h>
#include <cuda_bf16.h>

// TenHotEncodeLayer: out[n, t, x[n,t,f]] = 1.0 for f in [0,10); all else 0.
// x: [32, 512, 10] int32, out: [32, 512, 5000] float32 (flat 81,920,000).
//
// Strategy v8 (champion refinement): aligned flat-range partitioning,
// 8000 independent CTAs (oversubscribed — scheduler overlaps one CTA's
// barrier/patch tail with another's fill; persistent variant measured worse).
//   - Each CTA owns an aligned 2560-float4 (10240 B = 80 L2-line) range.
//   - Plain (cache-default) stores: keeps the range L2-resident so the
//     patch is a guaranteed L2 hit (evict-first __stcs measured no better
//     on the fill and risks DRAM round-trips for patched lines).
//   - All-int32 addressing: flat size 81.9M < 2^31, so no 64-bit chains
//     in the prologue before the first store issues.

#define NUM_TOKENS 5000
#define NUM_F 10
#define TPB 256
#define CTA_F4 2560                    // 10240 B, 128B-aligned
#define CTA_ELEMS (CTA_F4 * 4)         // 10240 floats
#define ITERS (CTA_F4 / TPB)           // 10, exact
#define GRID 8000                      // 20,480,000 f4 / 2560

__global__ __launch_bounds__(TPB) void tenhot_kernel(
    const int* __restrict__ x, float4* __restrict__ out)
{
    const int blk = blockIdx.x;
    const int tid = threadIdx.x;

    // Flat element range owned by this CTA: [s, s + CTA_ELEMS)  (fits int32)
    const int s = blk * CTA_ELEMS;
    const int row_lo = s / NUM_TOKENS;
    const int row_hi = (s + CTA_ELEMS - 1) / NUM_TOKENS;
    const int npatch = (row_hi - row_lo + 1) * NUM_F;   // <= 30

    // Prefetch scatter candidates before the fill (latency hidden).
    int flat = -1;
    if (tid < npatch) {
        int r = row_lo + tid / NUM_F;
        int f = tid - (tid / NUM_F) * NUM_F;
        int c = __ldg(&x[r * NUM_F + f]);
        int p = r * NUM_TOKENS + c;
        if (p >= s && p < s + CTA_ELEMS) flat = p;
    }

    // Aligned streaming fill: 10 x STG.128, each warp op = 4 full 128B lines.
    float4* o = out + (size_t)(unsigned)blk * CTA_F4;
    const float4 z = make_float4(0.f, 0.f, 0.f, 0.f);
#pragma unroll
    for (int k = 0; k < ITERS; k++)
        o[tid + TPB * k] = z;

    __syncthreads();

    if (flat >= 0)
        reinterpret_cast<float*>(out)[(size_t)(unsigned)flat] = 1.0f;
}

extern "C" void kernel_launch(void* const* d_in, const int* in_sizes, int n_in,
                              void* d_out, int out_size)
{
    const int* x = (const int*)d_in[0];
    float4* out = (float4*)d_out;
    tenhot_kernel<<<GRID, TPB>>>(x, out);
}

// round 9
// speedup vs baseline: 1.1626x; 1.0386x over previous
#include <cuda_runtime.h>
#include <cuda_bf16.h>

// TenHotEncodeLayer: out[n, t, x[n,t,f]] = 1.0 for f in [0,10); all else 0.
// x: [32, 512, 10] int32, out: [32, 512, 5000] float32 (flat 81,920,000 elems).
//
// FINAL (v6 champion, roofline-converged): aligned flat-range partitioning.
// Eight structural variants all plateau at 71-73% DRAM / ~7.0 TB/s effective
// write rate (~87% of HBM3e spec) — the write-stream roofline for this op.
//   - 8000 CTAs, each owning an aligned 2560-float4 (10240 B = 80 L2-line)
//     range; 256 threads x 10 unrolled STG.128, no tail, every warp store
//     = 4 full 128B lines, every line one owner. Oversubscription lets the
//     scheduler overlap one CTA's barrier/patch tail with another's fill
//     (persistent single-wave variant measured 13% worse).
//   - The range intersects <= 3 rows; <= 30 threads prefetch those rows'
//     indices before the fill (latency hidden), then after a block barrier
//     patch 1.0f at in-range flat positions (lines still L2-hot).

#define NUM_TOKENS 5000
#define NUM_F 10
#define TPB 256
#define CTA_F4 2560                    // 10240 B = 80 * 128B lines
#define CTA_ELEMS (CTA_F4 * 4)         // 10240 floats
#define ITERS (CTA_F4 / TPB)           // 10, exact
#define GRID 8000                      // 20,480,000 f4 / 2560

__global__ __launch_bounds__(TPB) void tenhot_kernel(
    const int* __restrict__ x, float4* __restrict__ out)
{
    const int blk = blockIdx.x;
    const int tid = threadIdx.x;

    // Flat element range owned by this CTA: [s, s + CTA_ELEMS)
    const long long s = (long long)blk * CTA_ELEMS;
    const int row_lo = (int)(s / NUM_TOKENS);
    const int row_hi = (int)((s + CTA_ELEMS - 1) / NUM_TOKENS);
    const int npatch = (row_hi - row_lo + 1) * NUM_F;   // <= 30

    // Prefetch scatter candidates before the fill (latency hidden).
    long long flat = -1;
    if (tid < npatch) {
        int r = row_lo + tid / NUM_F;
        int f = tid - (tid / NUM_F) * NUM_F;
        int c = __ldg(&x[r * NUM_F + f]);
        long long p = (long long)r * NUM_TOKENS + c;
        if (p >= s && p < s + CTA_ELEMS) flat = p;
    }

    // Aligned streaming fill: 10 x STG.128, each warp op = 4 full lines.
    float4* o = out + (size_t)blk * CTA_F4;
    const float4 z = make_float4(0.f, 0.f, 0.f, 0.f);
#pragma unroll
    for (int k = 0; k < ITERS; k++)
        __stcs(&o[tid + TPB * k], z);

    __syncthreads();

    if (flat >= 0)
        reinterpret_cast<float*>(out)[flat] = 1.0f;
}

extern "C" void kernel_launch(void* const* d_in, const int* in_sizes, int n_in,
                              void* d_out, int out_size)
{
    const int* x = (const int*)d_in[0];
    float4* out = (float4*)d_out;
    tenhot_kernel<<<GRID, TPB>>>(x, out);
}

// round 11
// speedup vs baseline: 1.1727x; 1.0087x over previous
#include <cuda_runtime.h>
#include <cuda_bf16.h>

// TenHotEncodeLayer: out[n, t, x[n,t,f]] = 1.0 for f in [0,10); all else 0.
// x: [32, 512, 10] int32, out: [32, 512, 5000] float32 (flat 81,920,000).
//
// Strategy v11: v10 (warp-ownership patching, no block barrier) with the
// candidate-enumeration bug fixed. A 10240-element range can intersect up
// to FOUR rows (npatch up to 40 > 32 lanes), so each lane scans candidates
// j = lane and j = lane + 32.
//   - Chunk c (= tid + 256k) is stored by warp (c>>5)&7; each warp patches
//     only positions in chunks it stored itself, so __syncwarp() (memory-
//     ordering among lanes) suffices — warps retire independently, no
//     CTA-wide barrier convoy.
//   - 8000 CTAs x 2560 float4 (10240 B = 80 L2 lines), 10 x STG.128 per
//     thread, evict-first, no tail.

#define NUM_TOKENS 5000
#define NUM_F 10
#define TPB 256
#define CTA_F4 2560                    // 10240 B, 128B-aligned
#define CTA_ELEMS (CTA_F4 * 4)
#define ITERS (CTA_F4 / TPB)           // 10, exact
#define GRID 8000

__global__ __launch_bounds__(TPB) void tenhot_kernel(
    const int* __restrict__ x, float4* __restrict__ out)
{
    const int blk  = blockIdx.x;
    const int tid  = threadIdx.x;
    const int warp = tid >> 5;
    const int lane = tid & 31;

    // Flat element range owned by this CTA: [s, s + CTA_ELEMS)
    const long long s = (long long)blk * CTA_ELEMS;
    const int row_lo = (int)(s / NUM_TOKENS);
    const int row_hi = (int)((s + CTA_ELEMS - 1) / NUM_TOKENS);
    const int npatch = (row_hi - row_lo + 1) * NUM_F;   // <= 40 (4 rows max)

    // Every warp scans ALL candidates (two per lane covers npatch <= 64);
    // keep those whose chunk THIS warp stores.
    long long flat0 = -1, flat1 = -1;
#pragma unroll
    for (int half = 0; half < 2; half++) {
        int j = lane + 32 * half;
        if (j < npatch) {
            int r = row_lo + j / NUM_F;
            int f = j - (j / NUM_F) * NUM_F;
            int c = __ldg(&x[r * NUM_F + f]);
            long long p = (long long)r * NUM_TOKENS + c;
            if (p >= s && p < s + CTA_ELEMS) {
                int chunk = (int)((p - s) >> 2);       // f4 chunk within range
                if (((chunk >> 5) & 7) == warp) {
                    if (half == 0) flat0 = p; else flat1 = p;
                }
            }
        }
    }

    // Aligned streaming fill: 10 x STG.128, each warp op = 4 full lines.
    float4* o = out + (size_t)blk * CTA_F4;
    const float4 z = make_float4(0.f, 0.f, 0.f, 0.f);
#pragma unroll
    for (int k = 0; k < ITERS; k++)
        __stcs(&o[tid + TPB * k], z);

    __syncwarp();   // orders this warp's zeros before its own patches

    if (flat0 >= 0)
        reinterpret_cast<float*>(out)[flat0] = 1.0f;
    if (flat1 >= 0)
        reinterpret_cast<float*>(out)[flat1] = 1.0f;
}

extern "C" void kernel_launch(void* const* d_in, const int* in_sizes, int n_in,
                              void* d_out, int out_size)
{
    const int* x = (const int*)d_in[0];
    float4* out = (float4*)d_out;
    tenhot_kernel<<<GRID, TPB>>>(x, out);
}